// round 14
// baseline (speedup 1.0000x reference)
#include <cuda_runtime.h>

#define Bz 2
#define Tz 2048
#define Hz 8
#define Dz 64
#define NBH (Bz * Hz)         // 16
#define ROWSTRIDE (Hz * Dz)   // 512 floats between consecutive t
#define GR 8                  // granule = time steps per warp in kernel B
#define NG (Tz / GR)          // 256 granules per (b,h)

// scratch: per-granule kf sums and their exclusive time-prefix (4 MB each)
__device__ float g_gsum[NBH * NG * Dz];
__device__ float g_gpre[NBH * NG * Dz];

__device__ __forceinline__ float fmap(float x) {
    return x > 0.f ? x + 1.f : __expf(x);   // elu(x)+1
}

// ---------------------------------------------------------------------------
// Kernel A: per-granule kf sums. grid (NBH, NG/8), block 256.
// Thread = (granule-sub gs = tid>>5, d-pair = tid&31); sums GR=8 rows.
// ---------------------------------------------------------------------------
__global__ void __launch_bounds__(256)
gsum_kernel(const float* __restrict__ k) {
    const int bh = blockIdx.x;
    const int b  = bh / Hz, h = bh % Hz;
    const int gs = threadIdx.x >> 5;          // 0..7
    const int l2 = threadIdx.x & 31;          // float2 lane
    const int g  = blockIdx.y * 8 + gs;
    const int t0 = g * GR;

    const float2* k2 = (const float2*)(k + ((long)b * Tz * Hz + (long)t0 * Hz + h) * Dz) + l2;

    float2 s = make_float2(0.f, 0.f);
    #pragma unroll
    for (int i = 0; i < GR; i++) {
        float2 kr = k2[i * (ROWSTRIDE / 2)];
        s.x += fmap(kr.x);  s.y += fmap(kr.y);
    }
    ((float2*)g_gsum)[((long)bh * NG + g) * (Dz / 2) + l2] = s;
}

// ---------------------------------------------------------------------------
// Kernel A2: exclusive scan of gsum over granules. grid NBH, block 256.
// Thread = (segment seg = tid>>5 of 32 granules, d-pair). Two passes + fixup.
// ---------------------------------------------------------------------------
__global__ void __launch_bounds__(256)
gscan_kernel() {
    const int bh  = blockIdx.x;
    const int seg = threadIdx.x >> 5;         // 0..7, 32 granules each
    const int l2  = threadIdx.x & 31;

    const float2* gs2 = (const float2*)g_gsum + ((long)bh * NG + seg * 32) * (Dz / 2) + l2;
    float2*       gp2 = (float2*)g_gpre       + ((long)bh * NG + seg * 32) * (Dz / 2) + l2;

    __shared__ float2 stot[8][32];

    // pass 1: segment total (batched loads for MLP)
    float2 tot = make_float2(0.f, 0.f);
    #pragma unroll
    for (int ii = 0; ii < 32; ii += 8) {
        float2 vbuf[8];
        #pragma unroll
        for (int j = 0; j < 8; j++) vbuf[j] = gs2[(ii + j) * (Dz / 2)];
        #pragma unroll
        for (int j = 0; j < 8; j++) { tot.x += vbuf[j].x;  tot.y += vbuf[j].y; }
    }
    stot[seg][l2] = tot;
    __syncthreads();

    // segment base = earlier segments' totals
    float2 run = make_float2(0.f, 0.f);
    #pragma unroll
    for (int s = 0; s < 7; s++) {
        if (s < seg) {
            float2 t = stot[s][l2];
            run.x += t.x;  run.y += t.y;
        }
    }

    // pass 2: write exclusive prefix (loads hit L1/L2)
    #pragma unroll
    for (int ii = 0; ii < 32; ii += 8) {
        float2 vbuf[8];
        #pragma unroll
        for (int j = 0; j < 8; j++) vbuf[j] = gs2[(ii + j) * (Dz / 2)];
        #pragma unroll
        for (int j = 0; j < 8; j++) {
            gp2[(ii + j) * (Dz / 2)] = run;
            run.x += vbuf[j].x;  run.y += vbuf[j].y;
        }
    }
}

// ---------------------------------------------------------------------------
// Kernel B: warp-centric, no block-level sync. grid (NBH, NG/8), block 256.
// Warp w owns granule blockIdx.y*8 + w: 8 time steps, lane owns d-pair.
// ---------------------------------------------------------------------------
__global__ void __launch_bounds__(256, 4)
attn_kernel(const float* __restrict__ q,
            const float* __restrict__ k,
            const float* __restrict__ v,
            float* __restrict__ out) {
    const int bh = blockIdx.x;
    const int b  = bh / Hz, h = bh % Hz;
    const int warp = threadIdx.x >> 5, lane = threadIdx.x & 31;
    const int g  = blockIdx.y * 8 + warp;
    const int t0 = g * GR;

    const long gbase = ((long)b * Tz * Hz + (long)t0 * Hz + h) * Dz;
    const float2* q2 = (const float2*)(q + gbase) + lane;
    const float2* k2 = (const float2*)(k + gbase) + lane;
    const float2* v2 = (const float2*)(v + gbase) + lane;
    float2*       o2 = (float2*)(out + gbase) + lane;

    // exclusive time-prefix of kf for this granule (one 8B load per lane)
    float2 cum = ((const float2*)g_gpre)[((long)bh * NG + g) * (Dz / 2) + lane];

    #pragma unroll
    for (int j = 0; j < GR; j++) {
        float2 kr = k2[j * (ROWSTRIDE / 2)];
        float2 qr = q2[j * (ROWSTRIDE / 2)];
        float2 vr = v2[j * (ROWSTRIDE / 2)];
        float2 kf = make_float2(fmap(kr.x), fmap(kr.y));
        float2 qf = make_float2(fmap(qr.x), fmap(qr.y));

        cum.x += kf.x;  cum.y += kf.y;        // inclusive cumK(t)

        // inclusive pair-scan of kf over d
        float ps   = kf.x + kf.y;
        float incl = ps;
        #pragma unroll
        for (int o = 1; o < 32; o <<= 1) {
            float t = __shfl_up_sync(0xFFFFFFFFu, incl, o);
            if (lane >= o) incl += t;
        }

        // partials: S = qf . prefK(t)   (prefK(d0) = incl - kf.y),  D = qf . cumK
        float Sp = qf.x * (incl - kf.y) + qf.y * incl;
        float dp = qf.x * cum.x + qf.y * cum.y;

        #pragma unroll
        for (int o = 16; o; o >>= 1) {
            Sp += __shfl_xor_sync(0xFFFFFFFFu, Sp, o);
            dp += __shfl_xor_sync(0xFFFFFFFFu, dp, o);
        }

        const float scale = Sp / dp;
        o2[j * (ROWSTRIDE / 2)] = make_float2(vr.x * scale, vr.y * scale);
    }
}

extern "C" void kernel_launch(void* const* d_in, const int* in_sizes, int n_in,
                              void* d_out, int out_size) {
    const float* q = (const float*)d_in[0];
    const float* k = (const float*)d_in[1];
    const float* v = (const float*)d_in[2];
    float* out = (float*)d_out;

    gsum_kernel<<<dim3(NBH, NG / 8), 256>>>(k);
    gscan_kernel<<<NBH, 256>>>();
    attn_kernel<<<dim3(NBH, NG / 8), 256>>>(q, k, v, out);
}

// round 17
// speedup vs baseline: 1.1376x; 1.1376x over previous
#include <cuda_runtime.h>

#define Bz 2
#define Tz 2048
#define Hz 8
#define Dz 64
#define CT 32                  // time steps per block (chunk)
#define NC (Tz / CT)           // 64 chunks per (b,h)
#define NBH (Bz * Hz)          // 16
#define ROWSTRIDE (Hz * Dz)    // 512 floats between consecutive t
#define TPW 4                  // time steps per warp (CT / 8 warps)

// per-chunk kf aggregates [bh][c][d]; zeroed each launch, elements strictly > 0
// once published (kf = elu+1 > 0), so "!= 0" doubles as the ready flag.
__device__ float g_agg[NBH * NC * Dz];

__device__ __forceinline__ float fmap(float x) {
    return x > 0.f ? x + 1.f : __expf(x);   // elu(x)+1
}

// ---------------------------------------------------------------------------
// zero scratch (64K floats). 64 blocks x 256 threads x float4.
// ---------------------------------------------------------------------------
__global__ void __launch_bounds__(256)
zero_kernel() {
    ((float4*)g_agg)[blockIdx.x * 256 + threadIdx.x] =
        make_float4(0.f, 0.f, 0.f, 0.f);
}

// ---------------------------------------------------------------------------
// Fused kernel: grid (NBH, NC), block 256 = 8 warps x TPW time steps.
// Lane owns d-pair (2*lane, 2*lane+1). Decoupled lookback for the time prefix.
// Deadlock-free: launch_bounds guarantees all 1024 blocks resident (7*148 >=
// 1024), and predecessors have lower linear block ids.
// ---------------------------------------------------------------------------
__global__ void __launch_bounds__(256, 7)
attn_fused(const float* __restrict__ q,
           const float* __restrict__ k,
           const float* __restrict__ v,
           float* __restrict__ out) {
    const int bh = blockIdx.x;
    const int c  = blockIdx.y;
    const int b  = bh / Hz, h = bh % Hz;
    const int warp = threadIdx.x >> 5, lane = threadIdx.x & 31;

    __shared__ float2 wsum[8][32];   // per-warp kf sums (this chunk)
    __shared__ float2 lsum[8][32];   // per-warp lookback partials

    const int  t0    = c * CT + warp * TPW;
    const long gbase = ((long)b * Tz * Hz + (long)t0 * Hz + h) * Dz;
    const float2* q2 = (const float2*)(q + gbase) + lane;
    const float2* k2 = (const float2*)(k + gbase) + lane;
    const float2* v2 = (const float2*)(v + gbase) + lane;
    float2*       o2 = (float2*)(out + gbase) + lane;

    // ---- phase 1: load this warp's rows (q,k,v), per-warp kf sum
    float2 kf[TPW], qf[TPW], vr[TPW];
    float2 ws = make_float2(0.f, 0.f);
    #pragma unroll
    for (int j = 0; j < TPW; j++) {
        float2 kr = k2[j * (ROWSTRIDE / 2)];
        float2 qr = q2[j * (ROWSTRIDE / 2)];
        vr[j]     = v2[j * (ROWSTRIDE / 2)];
        kf[j] = make_float2(fmap(kr.x), fmap(kr.y));
        qf[j] = make_float2(fmap(qr.x), fmap(qr.y));
        ws.x += kf[j].x;  ws.y += kf[j].y;
    }
    wsum[warp][lane] = ws;
    __syncthreads();

    // ---- phase 2a: warp 0 publishes the chunk aggregate (all elems > 0)
    if (warp == 0) {
        float2 agg = make_float2(0.f, 0.f);
        #pragma unroll
        for (int w = 0; w < 8; w++) {
            float2 t = wsum[w][lane];
            agg.x += t.x;  agg.y += t.y;
        }
        ((float2*)g_agg)[((long)bh * NC + c) * (Dz / 2) + lane] = agg;
    }

    // ---- phase 2b: distributed lookback over predecessor chunks (L2 polls)
    {
        const float2* ap = (const float2*)g_agg + (long)bh * NC * (Dz / 2) + lane;
        float2 a = make_float2(0.f, 0.f);
        for (int cc = warp; cc < c; cc += 8) {
            float2 t;
            t = __ldcg(ap + cc * (Dz / 2));
            while (t.x == 0.f || t.y == 0.f) {
                __nanosleep(32);
                t = __ldcg(ap + cc * (Dz / 2));
            }
            a.x += t.x;  a.y += t.y;
        }
        lsum[warp][lane] = a;
    }
    __syncthreads();

    // ---- exclusive time prefix for this warp's first step
    float2 cum = make_float2(0.f, 0.f);
    #pragma unroll
    for (int w = 0; w < 8; w++) {
        float2 t = lsum[w][lane];
        cum.x += t.x;  cum.y += t.y;
    }
    #pragma unroll
    for (int ww = 0; ww < 7; ww++) {
        if (ww < warp) {
            float2 t = wsum[ww][lane];
            cum.x += t.x;  cum.y += t.y;
        }
    }

    // ---- phase 3: per time step
    #pragma unroll
    for (int j = 0; j < TPW; j++) {
        cum.x += kf[j].x;  cum.y += kf[j].y;      // inclusive cumK(t)

        // inclusive pair-scan of kf over d
        float ps   = kf[j].x + kf[j].y;
        float incl = ps;
        #pragma unroll
        for (int o = 1; o < 32; o <<= 1) {
            float t = __shfl_up_sync(0xFFFFFFFFu, incl, o);
            if (lane >= o) incl += t;
        }

        // S = qf . prefK(t)  (prefK(d0) = incl - kf.y),  D = qf . cumK(t)
        float Sp = qf[j].x * (incl - kf[j].y) + qf[j].y * incl;
        float dp = qf[j].x * cum.x + qf[j].y * cum.y;

        #pragma unroll
        for (int o = 16; o; o >>= 1) {
            Sp += __shfl_xor_sync(0xFFFFFFFFu, Sp, o);
            dp += __shfl_xor_sync(0xFFFFFFFFu, dp, o);
        }

        const float scale = Sp / dp;
        o2[j * (ROWSTRIDE / 2)] = make_float2(vr[j].x * scale, vr[j].y * scale);
    }
}

extern "C" void kernel_launch(void* const* d_in, const int* in_sizes, int n_in,
                              void* d_out, int out_size) {
    const float* q = (const float*)d_in[0];
    const float* k = (const float*)d_in[1];
    const float* v = (const float*)d_in[2];
    float* out = (float*)d_out;

    zero_kernel<<<(NBH * NC * Dz) / 1024, 256>>>();
    attn_fused<<<dim3(NBH, NC), 256>>>(q, k, v, out);
}